// round 17
// baseline (speedup 1.0000x reference)
#include <cuda_runtime.h>
#include <cuda_bf16.h>
#include <math.h>
#include <stdint.h>

typedef __nv_bfloat16 bf16;

#define BB 1024
#define DD 128
#define WW 512
#define TT 8
#define NELEM (BB*DD)
#define HELEM (BB*WW)
#define MAX_STEPS 48
#define NBLK 256
#define NTHR 256
#define GCTA 16
#define RTOLc 1e-3f
#define ATOLc 1e-6f

#define SROWB 144
#define OA_LO  9216
#define OB_HI 18432
#define OB_LO 23040
#define BUFS  27648
#define NSTG 3
#define SMEM_DYN (NSTG*BUFS)

#define G3SET 13824
#define G3_ALO 2304
#define G3_BHI 4608
#define G3_BLO 9216

#define A21f 0.161f
#define A31f (-0.008480655492356989f)
#define A32f 0.335480655492357f
#define A41f 2.8971530571054935f
#define A42f (-6.359448489975075f)
#define A43f 4.3622954328695815f
#define A51f 5.325864828439257f
#define A52f (-11.748883564062828f)
#define A53f 7.4955393428898365f
#define A54f (-0.09249506636175525f)
#define A61f 5.86145544294642f
#define A62f (-12.92096931784711f)
#define A63f 8.159367898576159f
#define A64f (-0.071584973281401f)
#define A65f (-0.028269050394068383f)
#define Bc1 0.09646076681806523f
#define Bc2 0.01f
#define Bc3 0.4798896504144996f
#define Bc4 1.379008574103742f
#define Bc5 (-3.290069515436081f)
#define Bc6 2.324710524099774f
#define Ec1 (-0.00178001105222577714f)
#define Ec2 (-0.0008164344596567469f)
#define Ec3 0.007880878010261995f
#define Ec4 (-0.1447110071732629f)
#define Ec5 0.5823571654525552f
#define Ec6 (-0.45808210592918697f)
#define Ec7 0.015151515151515152f

// ---------------- device state ----------------
__device__ __align__(16) float g_yb[2][NELEM], g_k[7][NELEM];
__device__ __align__(16) bf16 g_Xhi[NELEM], g_Xlo[NELEM];
__device__ __align__(16) bf16 g_H1hi[HELEM], g_H1lo[HELEM];
__device__ __align__(16) bf16 g_H2hi[HELEM], g_H2lo[HELEM];
__device__ __align__(16) bf16 g_W0hi[WW*DD], g_W0lo[WW*DD];
__device__ __align__(16) bf16 g_W1hi[WW*WW], g_W1lo[WW*WW];
__device__ __align__(16) bf16 g_W2hi[DD*WW], g_W2lo[DD*WW];
__device__ double g_errpart[NBLK];
__device__ unsigned g_arrive;
__device__ volatile unsigned gg_flag[NBLK * 32];

__constant__ float c_coef[6][6] = {
  {A21f,0,0,0,0,0},
  {A31f,A32f,0,0,0,0},
  {A41f,A42f,A43f,0,0,0},
  {A51f,A52f,A53f,A54f,0,0},
  {A61f,A62f,A63f,A64f,A65f,0},
  {Bc1,Bc2,Bc3,Bc4,Bc5,Bc6},
};

// ---------------- helpers ----------------
__device__ __forceinline__ uint32_t smem_u32(const void* p) {
  uint32_t a;
  asm("{ .reg .u64 t; cvta.to.shared.u64 t, %1; cvt.u32.u64 %0, t; }" : "=r"(a) : "l"(p));
  return a;
}
__device__ __forceinline__ void cp16(uint32_t dst, const void* src) {
  asm volatile("cp.async.cg.shared.global [%0], [%1], 16;" :: "r"(dst), "l"(src) : "memory");
}
__device__ __forceinline__ void cp16ca(uint32_t dst, const void* src) {
  asm volatile("cp.async.ca.shared.global [%0], [%1], 16;" :: "r"(dst), "l"(src) : "memory");
}
__device__ __forceinline__ void cp_commit() { asm volatile("cp.async.commit_group;" ::: "memory"); }
__device__ __forceinline__ void cp_wait1() { asm volatile("cp.async.wait_group 1;" ::: "memory"); }
__device__ __forceinline__ void cp_wait0() { asm volatile("cp.async.wait_group 0;" ::: "memory"); }

#define LDMX4(r, addr) \
  asm volatile("ldmatrix.sync.aligned.m8n8.x4.shared.b16 {%0,%1,%2,%3}, [%4];" \
    : "=r"((r)[0]), "=r"((r)[1]), "=r"((r)[2]), "=r"((r)[3]) : "r"(addr))
#define LDMX2(r, addr) \
  asm volatile("ldmatrix.sync.aligned.m8n8.x2.shared.b16 {%0,%1}, [%2];" \
    : "=r"((r)[0]), "=r"((r)[1]) : "r"(addr))

__device__ __forceinline__ void mma16816(float* c, const uint32_t* a, const uint32_t* b) {
  asm volatile(
    "mma.sync.aligned.m16n8k16.row.col.f32.bf16.bf16.f32 "
    "{%0,%1,%2,%3}, {%4,%5,%6,%7}, {%8,%9}, {%0,%1,%2,%3};"
    : "+f"(c[0]), "+f"(c[1]), "+f"(c[2]), "+f"(c[3])
    : "r"(a[0]), "r"(a[1]), "r"(a[2]), "r"(a[3]), "r"(b[0]), "r"(b[1]));
}

// ---------------- barriers & flags ----------------
__device__ __forceinline__ void gsync() {
  __syncthreads();
  if (threadIdx.x == 0) {
    __threadfence();
    unsigned t = atomicAdd(&g_arrive, 1u) + 1u;
    unsigned target = ((t + NBLK - 1u) / NBLK) * NBLK;
    while (*(volatile unsigned*)&g_arrive < target) {}
    __threadfence();
  }
  __syncthreads();
}
__device__ __forceinline__ void ggsync(int grp, unsigned ep) {
  __syncthreads();
  if (threadIdx.x == 0) {
    __threadfence();
    gg_flag[blockIdx.x * 32] = ep;
  }
  if (threadIdx.x < GCTA) {
    const volatile unsigned* f = &gg_flag[(grp * GCTA + threadIdx.x) * 32];
    while (*f < ep) {}
  }
  __syncthreads();
}
// release-publish this CTA's epoch (no wait)
__device__ __forceinline__ void publish(unsigned val) {
  __syncthreads();
  if (threadIdx.x == 0) {
    __threadfence();
    gg_flag[blockIdx.x * 32] = val;
  }
}
// acquire-wait on a producer CTA pair (group-local pair index)
__device__ __forceinline__ void wait2(int grp, int pair, unsigned val) {
  const volatile unsigned* f0 = &gg_flag[(grp * GCTA + 2 * pair) * 32];
  const volatile unsigned* f1 = &gg_flag[(grp * GCTA + 2 * pair + 1) * 32];
  while (*f0 < val) {}
  while (*f1 < val) {}
  __threadfence();
}

// -------- MUFU-free softplus (abs err ~2e-6) --------
__device__ __forceinline__ float softplus_f(float x) {
  float t = fabsf(x);
  float s = fminf(t * 1.4426950408889634f, 100.f);
  float n = floorf(s);
  float r = n - s;
  float p = 1.3215487e-6f;
  p = fmaf(p, r, 1.5252734e-5f);
  p = fmaf(p, r, 1.5403530e-4f);
  p = fmaf(p, r, 1.3333558e-3f);
  p = fmaf(p, r, 9.6181291e-3f);
  p = fmaf(p, r, 5.5504109e-2f);
  p = fmaf(p, r, 2.4022651e-1f);
  p = fmaf(p, r, 6.9314718e-1f);
  p = fmaf(p, r, 1.0f);
  float u = p * __uint_as_float((uint32_t)(127 - (int)n) << 23);
  float d = 2.f + u;
  float w = fmaf(-0.1635f, u, 0.4915f);
  w = w * fmaf(-d, w, 2.f);
  w = w * fmaf(-d, w, 2.f);
  float v = u * w;
  float v2 = v * v;
  float g = 0.09090909f;
  g = fmaf(g, v2, 0.11111111f);
  g = fmaf(g, v2, 0.14285714f);
  g = fmaf(g, v2, 0.2f);
  g = fmaf(g, v2, 0.33333333f);
  g = fmaf(g, v2, 1.0f);
  return fmaxf(x, 0.f) + 2.f * v * g;
}

__device__ __forceinline__ void split_pack(float x0, float x1, uint32_t& hv, uint32_t& lv) {
  bf16 h0 = __float2bfloat16(x0), h1 = __float2bfloat16(x1);
  bf16 l0 = __float2bfloat16(x0 - __bfloat162float(h0));
  bf16 l1 = __float2bfloat16(x1 - __bfloat162float(h1));
  hv = (uint32_t)__bfloat16_as_ushort(h0) | ((uint32_t)__bfloat16_as_ushort(h1) << 16);
  lv = (uint32_t)__bfloat16_as_ushort(l0) | ((uint32_t)__bfloat16_as_ushort(l1) << 16);
}

// ---------------- GEMM1/2: C[64,32] = act(A[64,K] @ B[32,K]^T + bias) -> bf16 hi/lo ----------------
// WAITP: per-chunk producer-pair waits (chunk c <- group CTAs 2c,2c+1 at epoch >= wval)
template<int NC, bool SP, bool WAITP>
__device__ __forceinline__ void mma_gemm(
    const bf16* __restrict__ Ahi, const bf16* __restrict__ Alo,
    const bf16* __restrict__ Bhi, const bf16* __restrict__ Blo,
    int ldk, int bm, int bn,
    const float* __restrict__ bias,
    bf16* __restrict__ Chi, bf16* __restrict__ Clo, int ldc,
    char* sm, int grp, unsigned wval)
{
  const int tid = threadIdx.x;
  const int wid = tid >> 5;
  const int lane = tid & 31;
  const int grpL = lane >> 2, tig = lane & 3;
  const int wm = wid >> 1, wn = wid & 1;

  float hh[2][4] = {}, hl[2][4] = {}, lh[2][4] = {};

  int ar[4], as[4]; bool asel[4];
  #pragma unroll
  for (int i = 0; i < 4; ++i) {
    int lin = i * 256 + tid;
    asel[i] = lin >= 512;
    ar[i] = (lin >> 3) & 63;
    as[i] = (lin & 7) << 3;
  }
  int br[2], bs[2]; bool bsel[2];
  #pragma unroll
  for (int i = 0; i < 2; ++i) {
    int lin = i * 256 + tid;
    bsel[i] = lin >= 256;
    br[i] = (lin >> 3) & 31;
    bs[i] = (lin & 7) << 3;
  }
  const uint32_t smb = smem_u32(sm);
  uint32_t stA[4], stB[2];
  #pragma unroll
  for (int i = 0; i < 4; ++i) stA[i] = smb + (asel[i] ? OA_LO : 0) + ar[i] * SROWB + as[i] * 2;
  #pragma unroll
  for (int i = 0; i < 2; ++i) stB[i] = smb + (bsel[i] ? OB_LO : OB_HI) + br[i] * SROWB + bs[i] * 2;
  const bf16* gA[4]; const bf16* gB[2];
  #pragma unroll
  for (int i = 0; i < 4; ++i) gA[i] = (asel[i] ? Alo : Ahi) + (bm + ar[i]) * ldk + as[i];
  #pragma unroll
  for (int i = 0; i < 2; ++i) gB[i] = (bsel[i] ? Blo : Bhi) + (bn + br[i]) * ldk + bs[i];

  const uint32_t laA_hi = smb + (wm * 16 + (lane & 15)) * SROWB + ((lane >> 4) << 4);
  const uint32_t laA_lo = laA_hi + OA_LO;
  const uint32_t laB4_hi = smb + OB_HI + (wn * 16 + ((lane >> 4) << 3) + (lane & 7)) * SROWB
                           + (((lane >> 3) & 1) << 4);
  const uint32_t laB4_lo = laB4_hi + (OB_LO - OB_HI);

  if (WAITP) wait2(grp, 0, wval);
  #pragma unroll
  for (int i = 0; i < 4; ++i) cp16(stA[i], gA[i]);
  #pragma unroll
  for (int i = 0; i < 2; ++i) cp16ca(stB[i], gB[i]);
  cp_commit();
  if (NC > 1) {
    if (WAITP) wait2(grp, 1, wval);
    #pragma unroll
    for (int i = 0; i < 4; ++i) cp16(stA[i] + BUFS, gA[i] + 64);
    #pragma unroll
    for (int i = 0; i < 2; ++i) cp16ca(stB[i] + BUFS, gB[i] + 64);
    cp_commit();
  }

  if (NC == 2) {
    cp_wait0();
    __syncthreads();
    #pragma unroll
    for (int c = 0; c < 2; ++c) {
      const uint32_t bo = c ? BUFS : 0;
      #pragma unroll
      for (int ks = 0; ks < 4; ++ks) {
        uint32_t ah[4], al[4], b4h[4], b4l[4];
        LDMX4(ah, laA_hi + bo + ks * 32);
        LDMX4(al, laA_lo + bo + ks * 32);
        LDMX4(b4h, laB4_hi + bo + ks * 32);
        LDMX4(b4l, laB4_lo + bo + ks * 32);
        mma16816(hh[0], ah, b4h);
        mma16816(hl[0], ah, b4l);
        mma16816(lh[0], al, b4h);
        mma16816(hh[1], ah, b4h + 2);
        mma16816(hl[1], ah, b4l + 2);
        mma16816(lh[1], al, b4h + 2);
      }
    }
  } else {
    for (int c = 0; c < NC; ++c) {
      cp_wait1();
      __syncthreads();
      const uint32_t bo = (uint32_t)(c % NSTG) * BUFS;
      #pragma unroll
      for (int ks = 0; ks < 4; ++ks) {
        uint32_t ah[4], al[4], b4h[4], b4l[4];
        LDMX4(ah, laA_hi + bo + ks * 32);
        LDMX4(al, laA_lo + bo + ks * 32);
        LDMX4(b4h, laB4_hi + bo + ks * 32);
        LDMX4(b4l, laB4_lo + bo + ks * 32);
        mma16816(hh[0], ah, b4h);
        mma16816(hl[0], ah, b4l);
        mma16816(lh[0], al, b4h);
        mma16816(hh[1], ah, b4h + 2);
        mma16816(hl[1], ah, b4l + 2);
        mma16816(lh[1], al, b4h + 2);
      }
      if (c + 2 < NC) {
        if (WAITP) wait2(grp, c + 2, wval);
        const uint32_t bo2 = (uint32_t)((c + 2) % NSTG) * BUFS;
        int k0 = (c + 2) * 64;
        #pragma unroll
        for (int i = 0; i < 4; ++i) cp16(stA[i] + bo2, gA[i] + k0);
        #pragma unroll
        for (int i = 0; i < 2; ++i) cp16ca(stB[i] + bo2, gB[i] + k0);
      }
      cp_commit();
    }
  }

  #pragma unroll
  for (int ni = 0; ni < 2; ++ni) {
    int m0 = bm + wm * 16 + grpL;
    int n  = bn + wn * 16 + ni * 8 + tig * 2;
    float bv0 = __ldg(bias + n), bv1 = __ldg(bias + n + 1);
    float x0 = hh[ni][0] + hl[ni][0] + lh[ni][0] + bv0;
    float x1 = hh[ni][1] + hl[ni][1] + lh[ni][1] + bv1;
    float x2 = hh[ni][2] + hl[ni][2] + lh[ni][2] + bv0;
    float x3 = hh[ni][3] + hl[ni][3] + lh[ni][3] + bv1;
    if (SP) { x0 = softplus_f(x0); x1 = softplus_f(x1); x2 = softplus_f(x2); x3 = softplus_f(x3); }
    uint32_t hv, lv;
    split_pack(x0, x1, hv, lv);
    __stcg((uint32_t*)(Chi + m0 * ldc + n), hv);
    __stcg((uint32_t*)(Clo + m0 * ldc + n), lv);
    split_pack(x2, x3, hv, lv);
    __stcg((uint32_t*)(Chi + (m0 + 8) * ldc + n), hv);
    __stcg((uint32_t*)(Clo + (m0 + 8) * ldc + n), lv);
  }
}

// ---------------- GEMM3 (stage S): k tile [16,32], K=512, 6-set pipeline, fused epilogue ----------------
template<int S>
__device__ __forceinline__ void gemm3_stage(
    char* sm, float* sred,
    int bm, int bn, const float* __restrict__ b2, double* sd, float h,
    const float* __restrict__ yb, const float* __restrict__ ynb,
    int slot0, int kdst, int grp, unsigned wval)
{
  const int tid = threadIdx.x;
  const int wid = tid >> 5, lane = tid & 31;
  const int wn = wid & 3, wk = wid >> 2;
  const int grpL = lane >> 2, tig = lane & 3;

  float hh[4] = {}, hl[4] = {}, lh[4] = {};

  const bool aselt = tid >= 128;
  const int arow = (tid >> 3) & 15;
  const int aseg = (tid & 7) << 3;
  int br[2], bs[2]; bool bsel[2];
  #pragma unroll
  for (int i = 0; i < 2; ++i) {
    int lin = i * 256 + tid;
    bsel[i] = lin >= 256;
    br[i] = (lin >> 3) & 31;
    bs[i] = (lin & 7) << 3;
  }

  const uint32_t smb = smem_u32(sm);
  const uint32_t stAo = (aselt ? G3_ALO : 0) + arow * SROWB + aseg * 2;
  uint32_t stBo[2];
  #pragma unroll
  for (int i = 0; i < 2; ++i) stBo[i] = (bsel[i] ? G3_BLO : G3_BHI) + br[i] * SROWB + bs[i] * 2;
  const bf16* gA = (aselt ? g_H2lo : g_H2hi) + (bm + arow) * WW + aseg;
  const bf16* gB[2];
  #pragma unroll
  for (int i = 0; i < 2; ++i) gB[i] = (bsel[i] ? g_W2lo : g_W2hi) + (bn + br[i]) * WW + bs[i];

  const uint32_t laAo_hi = (lane & 15) * SROWB + ((lane >> 4) << 4);
  const uint32_t laAo_lo = laAo_hi + G3_ALO;
  const uint32_t laBo_hi = G3_BHI + (wn * 8 + (lane & 7)) * SROWB + (((lane >> 3) & 1) << 4);
  const uint32_t laBo_lo = laBo_hi + (G3_BLO - G3_BHI);

  #pragma unroll
  for (int p = 0; p < 2; ++p) {
    #pragma unroll
    for (int q = 0; q < 2; ++q) {
      int ck = p * 2 + q;
      wait2(grp, ck, wval);
      uint32_t setb = smb + (uint32_t)ck * G3SET;
      cp16(setb + stAo, gA + ck * 64);
      cp16ca(setb + stBo[0], gB[0] + ck * 64);
      cp16ca(setb + stBo[1], gB[1] + ck * 64);
    }
    cp_commit();
  }

  for (int i = 0; i < 4; ++i) {
    cp_wait1();
    __syncthreads();
    #pragma unroll
    for (int cc = 0; cc < 2; ++cc) {
      const int chunk = 2 * i + cc;
      const uint32_t setb = smb + (uint32_t)(chunk % 6) * G3SET;
      #pragma unroll
      for (int ks2 = 0; ks2 < 2; ++ks2) {
        const int ks = wk * 2 + ks2;
        uint32_t ah[4], al[4], bh[2], bl[2];
        LDMX4(ah, setb + laAo_hi + ks * 32);
        LDMX4(al, setb + laAo_lo + ks * 32);
        LDMX2(bh, setb + laBo_hi + ks * 32);
        LDMX2(bl, setb + laBo_lo + ks * 32);
        mma16816(hh, ah, bh);
        mma16816(hl, ah, bl);
        mma16816(lh, al, bh);
      }
    }
    const int pc = 2 * i + 4;
    if (pc < 8) {
      #pragma unroll
      for (int q = 0; q < 2; ++q) {
        int ck = pc + q;
        wait2(grp, ck, wval);
        uint32_t setb = smb + (uint32_t)(ck % 6) * G3SET;
        cp16(setb + stAo, gA + ck * 64);
        cp16ca(setb + stBo[0], gB[0] + ck * 64);
        cp16ca(setb + stBo[1], gB[1] + ck * 64);
      }
    }
    cp_commit();
  }

  float acc[4];
  #pragma unroll
  for (int j = 0; j < 4; ++j) acc[j] = hh[j] + hl[j] + lh[j];

  const int nl = wn * 8 + tig * 2;
  if (wk == 1) {
    sred[grpL * 32 + nl]           = acc[0];
    sred[grpL * 32 + nl + 1]       = acc[1];
    sred[(grpL + 8) * 32 + nl]     = acc[2];
    sred[(grpL + 8) * 32 + nl + 1] = acc[3];
  }
  __syncthreads();
  double ss = 0.0;
  if (wk == 0) {
    acc[0] += sred[grpL * 32 + nl];
    acc[1] += sred[grpL * 32 + nl + 1];
    acc[2] += sred[(grpL + 8) * 32 + nl];
    acc[3] += sred[(grpL + 8) * 32 + nl + 1];

    const int n0 = bn + nl;
    const int m0 = bm + grpL;
    const int i0 = m0 * DD + n0;
    const int i1 = (m0 + 8) * DD + n0;
    float bv0 = __ldg(b2 + n0), bv1 = __ldg(b2 + n0 + 1);
    float2 v0 = {acc[0] + bv0, acc[1] + bv1};
    float2 v1 = {acc[2] + bv0, acc[3] + bv1};
    float* kout = g_k[0] + (size_t)kdst * NELEM;
    __stcg((float2*)(kout + i0), v0);
    __stcg((float2*)(kout + i1), v1);

    const int idxs[2] = {i0, i1};
    const float2 vs[2] = {v0, v1};
    if constexpr (S <= 5) {
      #pragma unroll
      for (int r = 0; r < 2; ++r) {
        int ix = idxs[r];
        float2 y2 = __ldcg((const float2*)(yb + ix));
        float cS = c_coef[S][S];
        float ax = cS * vs[r].x, ay = cS * vs[r].y;
        #pragma unroll
        for (int j = 0; j < S; ++j) {
          float cj = c_coef[S][j];
          const float* kj_p = (j == 0) ? (g_k[0] + (size_t)slot0 * NELEM) : g_k[j];
          float2 kj = __ldcg((const float2*)(kj_p + ix));
          ax = fmaf(cj, kj.x, ax);
          ay = fmaf(cj, kj.y, ay);
        }
        float Xx = fmaf(h, ax, y2.x);
        float Xy = fmaf(h, ay, y2.y);
        if constexpr (S == 5) {
          float2 yn = {Xx, Xy};
          __stcg((float2*)(const_cast<float*>(ynb) + ix), yn);
        }
        uint32_t hv, lv;
        split_pack(Xx, Xy, hv, lv);
        __stcg((uint32_t*)(g_Xhi + ix), hv);
        __stcg((uint32_t*)(g_Xlo + ix), lv);
      }
    } else {
      #pragma unroll
      for (int r = 0; r < 2; ++r) {
        int ix = idxs[r];
        float2 k0 = __ldcg((const float2*)(g_k[0] + (size_t)slot0 * NELEM + ix));
        float2 k1 = __ldcg((const float2*)(g_k[1] + ix));
        float2 k2 = __ldcg((const float2*)(g_k[2] + ix));
        float2 k3 = __ldcg((const float2*)(g_k[3] + ix));
        float2 k4 = __ldcg((const float2*)(g_k[4] + ix));
        float2 k5 = __ldcg((const float2*)(g_k[5] + ix));
        float2 y2 = __ldcg((const float2*)(yb + ix));
        float2 yn = __ldcg((const float2*)(ynb + ix));
        #pragma unroll
        for (int cc = 0; cc < 2; ++cc) {
          float e = Ec1 * (cc ? k0.y : k0.x);
          e = fmaf(Ec2, cc ? k1.y : k1.x, e);
          e = fmaf(Ec3, cc ? k2.y : k2.x, e);
          e = fmaf(Ec4, cc ? k3.y : k3.x, e);
          e = fmaf(Ec5, cc ? k4.y : k4.x, e);
          e = fmaf(Ec6, cc ? k5.y : k5.x, e);
          e = fmaf(Ec7, cc ? vs[r].y : vs[r].x, e);
          float err = h * e;
          float yv = cc ? y2.y : y2.x, ynv = cc ? yn.y : yn.x;
          float scale = ATOLc + RTOLc * fmaxf(fabsf(yv), fabsf(ynv));
          float rr = err / scale;
          ss += (double)rr * (double)rr;
        }
      }
    }
  }
  if constexpr (S == 6) {
    sd[tid] = ss;
    __syncthreads();
    #pragma unroll
    for (int s2 = 128; s2 > 0; s2 >>= 1) {
      if (tid < s2) sd[tid] += sd[tid + s2];
      __syncthreads();
    }
    if (tid == 0) *(volatile double*)&g_errpart[blockIdx.x] = sd[0];
  }
}

// ---------------- one RK stage (producer-consumer flags; 1 group barrier) ----------------
template<int S>
__device__ __forceinline__ void do_stage(int grp_id, int lbid, unsigned& ep, float h,
    const float* b0, const float* b1, const float* b2,
    char* sm, float* sred, double* sd,
    const float* yb, const float* ynb, int slot0, int kdst)
{
  const int bm = grp_id << 6;
  const int bn = lbid << 5;
  const unsigned v1 = ep++;
  const unsigned v2 = ep++;
  mma_gemm<2, true, false>(g_Xhi, g_Xlo, g_W0hi, g_W0lo, DD, bm, bn, b0,
                           g_H1hi, g_H1lo, WW, sm, grp_id, 0);
  publish(v1);
  mma_gemm<8, true, true>(g_H1hi, g_H1lo, g_W1hi, g_W1lo, WW, bm, bn, b1,
                          g_H2hi, g_H2lo, WW, sm, grp_id, v1);
  publish(v2);
  gemm3_stage<S>(sm, sred, bm + ((lbid >> 2) << 4), (lbid & 3) << 5, b2, sd, h,
                 yb, ynb, slot0, kdst, grp_id, v2);
  if (S < 6) ggsync(grp_id, ep++);
}

// update: out write on hit; build X for first live stage: X = y + a21h * k1
__device__ __forceinline__ void update_phase(int gid2, float* __restrict__ out,
                                             int hit, int wrow,
                                             const float* __restrict__ yb,
                                             const float* __restrict__ k1p,
                                             float a21h) {
  float2 yv = __ldcg((const float2*)(yb + gid2));
  if (hit) *(float2*)(out + wrow * NELEM + gid2) = yv;
  float2 k1 = __ldcg((const float2*)(k1p + gid2));
  float Xx = fmaf(a21h, k1.x, yv.x);
  float Xy = fmaf(a21h, k1.y, yv.y);
  uint32_t hv, lv;
  split_pack(Xx, Xy, hv, lv);
  __stcg((uint32_t*)(g_Xhi + gid2), hv);
  __stcg((uint32_t*)(g_Xlo + gid2), lv);
}

// ---------------- persistent solver ----------------
__global__ void __launch_bounds__(NTHR, 2) solve_kernel(
    const float* __restrict__ ts,
    const float* __restrict__ b0, const float* __restrict__ b1,
    const float* __restrict__ b2, float* __restrict__ out)
{
  extern __shared__ __align__(16) char sm[];
  __shared__ float sred[16 * 32];
  __shared__ double sd[NTHR];

  const int bid = blockIdx.x;
  const int tid = threadIdx.x;
  const int grp_id = bid >> 4;
  const int lbid = bid & 15;
  const int gid2 = (bid * NTHR + tid) * 2;
  unsigned ep = 1;

  float t = __ldg(ts + 0);
  float dt = __ldg(ts + 1) - t;
  int si = 1, done = 0, hit = 0, wrow = 0, sic = 1;
  int par = 0, slot0 = 0, slot6 = 6;
  float tns = __ldg(ts + 1);
  float h = fmaxf(fminf(dt, tns - t), 0.f);

  for (int step = 0; step < MAX_STEPS; ++step) {
    if (done) break;

    const float* yb = g_yb[par];
    const float* ynb = g_yb[par ^ 1];
    float a21h = (step == 0) ? 0.f : h * A21f;
    update_phase(gid2, out, hit, wrow, yb, g_k[0] + (size_t)slot0 * NELEM, a21h);
    ggsync(grp_id, ep++);

    if (step == 0)
      do_stage<0>(grp_id, lbid, ep, h, b0, b1, b2, sm, sred, sd, yb, ynb, slot0, slot0);
    do_stage<1>(grp_id, lbid, ep, h, b0, b1, b2, sm, sred, sd, yb, ynb, slot0, 1);
    do_stage<2>(grp_id, lbid, ep, h, b0, b1, b2, sm, sred, sd, yb, ynb, slot0, 2);
    do_stage<3>(grp_id, lbid, ep, h, b0, b1, b2, sm, sred, sd, yb, ynb, slot0, 3);
    do_stage<4>(grp_id, lbid, ep, h, b0, b1, b2, sm, sred, sd, yb, ynb, slot0, 4);
    do_stage<5>(grp_id, lbid, ep, h, b0, b1, b2, sm, sred, sd, yb, ynb, slot0, 5);
    do_stage<6>(grp_id, lbid, ep, h, b0, b1, b2, sm, sred, sd, yb, ynb, slot0, slot6);

    gsync();

    sd[tid] = *(volatile double*)&g_errpart[tid];
    __syncthreads();
    #pragma unroll
    for (int s2 = 128; s2 > 0; s2 >>= 1) {
      if (tid < s2) sd[tid] += sd[tid + s2];
      __syncthreads();
    }
    const double total = sd[0];
    __syncthreads();

    float enorm = sqrtf((float)(total / (double)NELEM));
    int accept = (enorm <= 1.0f) && !done;
    float t_new = t + h;
    hit = accept && (t_new >= tns - 1e-6f);
    if (accept) t = t_new;
    wrow = sic;
    si += hit;
    float factor;
    if (enorm > 0.f) {
      factor = 0.9f * powf(enorm, -0.2f);
      factor = fminf(fmaxf(factor, 0.2f), 10.f);
    } else factor = 10.f;
    if (!done) dt = dt * factor;
    if (accept) {
      par ^= 1;
      int tmp = slot0; slot0 = slot6; slot6 = tmp;
    }
    done = (si >= TT) ? 1 : 0;
    sic = si < (TT - 1) ? si : (TT - 1);
    tns = __ldg(ts + sic);
    h = done ? 0.f : fmaxf(fminf(dt, tns - t), 0.f);
  }
  if (hit) {
    float2 v = __ldcg((const float2*)(g_yb[par] + gid2));
    *(float2*)(out + wrow * NELEM + gid2) = v;
  }
}

// ---------------- init ----------------
__global__ void init_kernel(const float* __restrict__ ts, const float* __restrict__ y0,
                            const float* __restrict__ W0, const float* __restrict__ W1,
                            const float* __restrict__ W2, float* __restrict__ out)
{
  int idx = blockIdx.x * NTHR + threadIdx.x;
  if (idx < TT * NELEM) out[idx] = (idx < NELEM) ? y0[idx] : 0.f;
  if (idx < NELEM) {
    float v = y0[idx];
    g_yb[0][idx] = v;
    bf16 h = __float2bfloat16(v);
    g_Xhi[idx] = h;
    g_Xlo[idx] = __float2bfloat16(v - __bfloat162float(h));
  }
  if (idx < WW * DD) {
    float w = W0[idx];
    bf16 h = __float2bfloat16(w);
    g_W0hi[idx] = h; g_W0lo[idx] = __float2bfloat16(w - __bfloat162float(h));
    float w2 = W2[idx];
    bf16 h2 = __float2bfloat16(w2);
    g_W2hi[idx] = h2; g_W2lo[idx] = __float2bfloat16(w2 - __bfloat162float(h2));
  }
  if (idx < WW * WW) {
    float w = W1[idx];
    bf16 h = __float2bfloat16(w);
    g_W1hi[idx] = h; g_W1lo[idx] = __float2bfloat16(w - __bfloat162float(h));
  }
  if (idx < NBLK * 32) gg_flag[idx] = 0u;
  if (idx < NBLK) g_errpart[idx] = 0.0;
  if (idx == 0) g_arrive = 0u;
}

extern "C" void kernel_launch(void* const* d_in, const int* in_sizes, int n_in,
                              void* d_out, int out_size) {
  const float* ts = (const float*)d_in[0];
  const float* y0 = (const float*)d_in[1];
  const float* W0 = (const float*)d_in[2];
  const float* b0 = (const float*)d_in[3];
  const float* W1 = (const float*)d_in[4];
  const float* b1 = (const float*)d_in[5];
  const float* W2 = (const float*)d_in[6];
  const float* b2 = (const float*)d_in[7];
  float* out = (float*)d_out;

  cudaFuncSetAttribute(solve_kernel, cudaFuncAttributeMaxDynamicSharedMemorySize, SMEM_DYN);

  init_kernel<<<(TT * NELEM) / NTHR, NTHR>>>(ts, y0, W0, W1, W2, out);
  solve_kernel<<<NBLK, NTHR, SMEM_DYN>>>(ts, b0, b1, b2, out);
}